// round 14
// baseline (speedup 1.0000x reference)
#include <cuda_runtime.h>
#include <cstdint>

#define NB 1024
#define NC 500000
#define ND 64
#define NK 50
#define NR 148                 // sweep CTAs = one per SM
#define RC 3456                // columns per range = 27 tiles x 128
#define TPT 27
#define NPAD (NR * RC)         // 511488 padded rows
#define CAP 6144               // per-query candidate capacity
#define QS 25.0f
#define NSMP 4096              // tau sample size
#define SSTRIDE 122            // 4095*122 = 499590 < NC
#define NTAU 8                 // tau = 8th smallest sample score (~976 qualifiers)

typedef unsigned int u32;

// ------------------------- device-global scratch ---------------------------
__device__ __align__(16) unsigned char g_t8[(size_t)NPAD * 64];  // packed int8 table
__device__ int g_nint[NPAD];                                     // int norms (pad huge)
__device__ __align__(16) unsigned char g_q8[NB * 64];            // packed int8 queries
__device__ int g_tau[NB];                                        // per-query threshold
__device__ u32 g_cnt[NB];                                        // per-query counts
__device__ int g_cand[(size_t)NB * CAP];                         // candidate rows

// ------------------------------ helpers ------------------------------------
__device__ __forceinline__ u32 smem_u32(const void* p) {
    u32 a;
    asm("{ .reg .u64 t; cvta.to.shared.u64 t, %1; cvt.u32.u64 %0, t; }" : "=r"(a) : "l"(p));
    return a;
}
__device__ __forceinline__ void cpa16(u32 s, const void* g) {
    asm volatile("cp.async.cg.shared.global [%0], [%1], 16;" :: "r"(s), "l"(g));
}
__device__ __forceinline__ void cpa_commit() { asm volatile("cp.async.commit_group;" ::: "memory"); }
__device__ __forceinline__ void cpa_wait2()  { asm volatile("cp.async.wait_group 2;" ::: "memory"); }

__device__ __forceinline__ void quant_row(const float* v, u32* w, int& nint) {
    nint = 0;
#pragma unroll
    for (int j = 0; j < 16; j++) {
        u32 pk = 0;
#pragma unroll
        for (int e = 0; e < 4; e++) {
            int r = __float2int_rn(v[j * 4 + e] * QS);
            r = max(-127, min(127, r));
            nint += r * r;
            pk |= ((u32)(r & 255)) << (8 * e);
        }
        w[j] = pk;
    }
}
__device__ __forceinline__ void load16(const unsigned char* src, u32* w) {
    const uint4* p = (const uint4*)src;
#pragma unroll
    for (int i = 0; i < 4; i++) {
        uint4 x = p[i];
        w[4 * i] = x.x; w[4 * i + 1] = x.y; w[4 * i + 2] = x.z; w[4 * i + 3] = x.w;
    }
}

// ---------------------------------------------------------------------------
// prep_t: fp32 table -> packed int8 rows + int norms (padded rows never qualify)
// ---------------------------------------------------------------------------
__global__ void __launch_bounds__(256)
prep_t(const float* __restrict__ tkeys) {
    const int p = blockIdx.x * 256 + threadIdx.x;   // grid covers NPAD exactly
    u32 w[16];
    int nint;
    if (p < NC) {
        float v[ND];
        const float4* sp = (const float4*)(tkeys + (size_t)p * ND);
#pragma unroll
        for (int i = 0; i < 16; i++) {
            float4 x = __ldg(sp + i);
            v[4 * i] = x.x; v[4 * i + 1] = x.y; v[4 * i + 2] = x.z; v[4 * i + 3] = x.w;
        }
        quant_row(v, w, nint);
    } else {
#pragma unroll
        for (int i = 0; i < 16; i++) w[i] = 0;
        nint = 1 << 29;                              // never below any tau
    }
    uint4* dst = (uint4*)(g_t8 + (size_t)p * 64);
    dst[0] = make_uint4(w[0], w[1], w[2], w[3]);
    dst[1] = make_uint4(w[4], w[5], w[6], w[7]);
    dst[2] = make_uint4(w[8], w[9], w[10], w[11]);
    dst[3] = make_uint4(w[12], w[13], w[14], w[15]);
    g_nint[p] = nint;
}

// prep_q: quantize queries
__global__ void __launch_bounds__(256)
prep_q(const float* __restrict__ keys) {
    const int p = blockIdx.x * 256 + threadIdx.x;
    if (p >= NB) return;
    float v[ND];
    const float4* sp = (const float4*)(keys + (size_t)p * ND);
#pragma unroll
    for (int i = 0; i < 16; i++) {
        float4 x = __ldg(sp + i);
        v[4 * i] = x.x; v[4 * i + 1] = x.y; v[4 * i + 2] = x.z; v[4 * i + 3] = x.w;
    }
    u32 w[16]; int nint;
    quant_row(v, w, nint);
    uint4* dst = (uint4*)(g_q8 + (size_t)p * 64);
    dst[0] = make_uint4(w[0], w[1], w[2], w[3]);
    dst[1] = make_uint4(w[4], w[5], w[6], w[7]);
    dst[2] = make_uint4(w[8], w[9], w[10], w[11]);
    dst[3] = make_uint4(w[12], w[13], w[14], w[15]);
}

// ---------------------------------------------------------------------------
// tau_kernel: per-query threshold from 4096-row sample; also resets counter
// ---------------------------------------------------------------------------
__global__ void __launch_bounds__(256)
tau_kernel() {
    __shared__ int s_s[NSMP];                 // 16KB sample scores
    __shared__ int rv[8], rp[8];
    __shared__ int s_tau;

    const int q = blockIdx.x, tid = threadIdx.x;
    const int w = tid >> 5, lane = tid & 31;

    u32 qw[16];
    load16(g_q8 + (size_t)q * 64, qw);

#pragma unroll
    for (int i = 0; i < NSMP / 256; i++) {
        const int j = tid + i * 256;
        const int r = j * SSTRIDE;
        u32 tw[16];
        load16(g_t8 + (size_t)r * 64, tw);
        int d = 0;
#pragma unroll
        for (int k = 0; k < 16; k++) d = __dp4a((int)tw[k], (int)qw[k], d);
        s_s[j] = g_nint[r] - 2 * d;
    }
    __syncthreads();

    for (int k = 0; k < NTAU; k++) {
        int v = 0x7FFFFFFF, p = 0;
        for (int i = tid; i < NSMP; i += 256)
            if (s_s[i] < v) { v = s_s[i]; p = i; }
#pragma unroll
        for (int o = 16; o > 0; o >>= 1) {
            int ov = __shfl_down_sync(0xffffffffu, v, o);
            int op = __shfl_down_sync(0xffffffffu, p, o);
            if (ov < v) { v = ov; p = op; }
        }
        if (lane == 0) { rv[w] = v; rp[w] = p; }
        __syncthreads();
        if (tid == 0) {
            int bv = rv[0], bp = rp[0];
#pragma unroll
            for (int x = 1; x < 8; x++)
                if (rv[x] < bv) { bv = rv[x]; bp = rp[x]; }
            s_s[bp] = 0x7FFFFFFF;
            if (k == NTAU - 1) s_tau = bv;
        }
        __syncthreads();
    }
    if (tid == 0) { g_tau[q] = s_tau; g_cnt[q] = 0u; }
}

// ---------------------------------------------------------------------------
// sweep: dp4a sweep, SW-pipelined column loads, 8 independent dp4a chains
// 148 CTAs x 512 threads, 2 queries/thread
// ---------------------------------------------------------------------------
__global__ void __launch_bounds__(512)
sweep_kernel() {
    __shared__ __align__(16) u32 s_t[3][2048];   // 3 x 8KB tile
    __shared__ __align__(16) int s_n[3][128];

    const int tid = threadIdx.x;
    const int range = blockIdx.x;
    const int q0 = tid * 2, q1 = q0 + 1;
    const u32 sbt = smem_u32(&s_t[0][0]);
    const u32 sbn = smem_u32(&s_n[0][0]);

    u32 q0w[16], q1w[16];
    load16(g_q8 + (size_t)q0 * 64, q0w);
    load16(g_q8 + (size_t)q1 * 64, q1w);
    const int t0 = g_tau[q0] + 1;     // strict < t  <=>  s <= tau
    const int t1 = g_tau[q1] + 1;

    const size_t rbase = (size_t)range * RC;
    auto prefetch = [&](int t, int st) {
        const unsigned char* src = g_t8 + (rbase + (size_t)t * 128) * 64;
        cpa16(sbt + st * 8192 + tid * 16, src + tid * 16);
        if (tid < 32)
            cpa16(sbn + st * 512 + tid * 16,
                  (const unsigned char*)(g_nint + rbase + (size_t)t * 128) + tid * 16);
        cpa_commit();
    };

    prefetch(0, 0); prefetch(1, 1); prefetch(2, 2);

// load 2 columns (c, c+1) + norms into u32[16] register buffers
#define LOADC(X, Y, NX, NY, C)                                      \
    {                                                               \
        load16((const unsigned char*)(tp + (C) * 16), X);           \
        load16((const unsigned char*)(tp + ((C) + 1) * 16), Y);     \
        NX = np[(C)]; NY = np[(C) + 1];                             \
    }

// score 2 columns vs 2 queries with 8 independent dp4a chains; append
#define COMPUTE(X, Y, NX, NY, C)                                    \
    {                                                               \
        int a0a = 0, a0b = 0, b0a = 0, b0b = 0;                     \
        int a1a = 0, a1b = 0, b1a = 0, b1b = 0;                     \
        _Pragma("unroll")                                           \
        for (int j = 0; j < 8; j++) {                               \
            a0a = __dp4a((int)X[j],     (int)q0w[j],     a0a);      \
            b0a = __dp4a((int)Y[j],     (int)q0w[j],     b0a);      \
            a1a = __dp4a((int)X[j],     (int)q1w[j],     a1a);      \
            b1a = __dp4a((int)Y[j],     (int)q1w[j],     b1a);      \
            a0b = __dp4a((int)X[j + 8], (int)q0w[j + 8], a0b);      \
            b0b = __dp4a((int)Y[j + 8], (int)q0w[j + 8], b0b);      \
            a1b = __dp4a((int)X[j + 8], (int)q1w[j + 8], a1b);      \
            b1b = __dp4a((int)Y[j + 8], (int)q1w[j + 8], b1b);      \
        }                                                           \
        const int sa0 = NX - 2 * (a0a + a0b);                       \
        const int sb0 = NY - 2 * (b0a + b0b);                       \
        const int sa1 = NX - 2 * (a1a + a1b);                       \
        const int sb1 = NY - 2 * (b1a + b1b);                       \
        const int m = min(min(sa0, sb0) - t0, min(sa1, sb1) - t1);  \
        if (m < 0) {                                                \
            const int p0 = pbase + (C);                             \
            if (sa0 < t0) {                                         \
                u32 i = atomicAdd(&g_cnt[q0], 1u);                  \
                if (i < CAP) g_cand[(size_t)q0 * CAP + i] = p0;     \
            }                                                       \
            if (sb0 < t0) {                                         \
                u32 i = atomicAdd(&g_cnt[q0], 1u);                  \
                if (i < CAP) g_cand[(size_t)q0 * CAP + i] = p0 + 1; \
            }                                                       \
            if (sa1 < t1) {                                         \
                u32 i = atomicAdd(&g_cnt[q1], 1u);                  \
                if (i < CAP) g_cand[(size_t)q1 * CAP + i] = p0;     \
            }                                                       \
            if (sb1 < t1) {                                         \
                u32 i = atomicAdd(&g_cnt[q1], 1u);                  \
                if (i < CAP) g_cand[(size_t)q1 * CAP + i] = p0 + 1; \
            }                                                       \
        }                                                           \
    }

    for (int t = 0; t < TPT; t++) {
        const int st = t % 3;
        cpa_wait2();
        __syncthreads();

        const u32* tp = s_t[st];
        const int* np = s_n[st];
        const int pbase = range * RC + t * 128;

        u32 A[16], B[16];
        int nA0, nA1, nB0, nB1;

        LOADC(A, B, nA0, nA1, 0);   // A<-col0, B<-col1 packaged as pair (0,1)
        // reinterpret: LOADC(X,Y,..) loads cols C and C+1 into X and Y.
        // We pipeline at 2-col granularity with two buffers: (A,B) and (C2,D2).
        u32 C2[16], D2[16];
        int nC0, nC1;
#pragma unroll 4
        for (int c = 0; c < 128; c += 4) {
            LOADC(C2, D2, nC0, nC1, c + 2);
            COMPUTE(A, B, nA0, nA1, c);
            LOADC(A, B, nA0, nA1, (c + 4) & 127);
            COMPUTE(C2, D2, nC0, nC1, c + 2);
        }

        __syncthreads();
        if (t + 3 < TPT) prefetch(t + 3, st);
        else cpa_commit();
    }
#undef LOADC
#undef COMPUTE
}

// ---------------------------------------------------------------------------
// merge: exact fp32 rerank (ILP-2) -> exact top-50 -> weighted average
// ---------------------------------------------------------------------------
__global__ void __launch_bounds__(256)
merge_kernel(const float* __restrict__ keys, const float* __restrict__ tkeys,
             const float* __restrict__ tvals, float* __restrict__ out) {
    __shared__ float sd[CAP];                 // 24KB exact distances
    __shared__ __align__(16) float qs[ND];
    __shared__ float frv[8]; __shared__ int frp[8];
    __shared__ float selv[NK]; __shared__ int sel2[NK];
    __shared__ float ws[NK], wv[NK];

    const int q = blockIdx.x, tid = threadIdx.x;
    const int w = tid >> 5, lane = tid & 31;
    const float INF = __int_as_float(0x7f800000);
    const int n = min((int)g_cnt[q], CAP);
    const int* cand = g_cand + (size_t)q * CAP;

    if (tid < ND) qs[tid] = keys[(size_t)q * ND + tid];
    __syncthreads();

    // exact squared distances: warp per candidate, 2 rows in flight
    {
        const float2 qv = ((const float2*)qs)[lane];
        for (int cb = w; cb < n; cb += 16) {
            const int cb2 = cb + 8;
            const bool has2 = cb2 < n;
            const int ra = cand[cb];
            const int rb = cand[has2 ? cb2 : cb];
            const float2 ta = ((const float2*)(tkeys + (size_t)ra * ND))[lane];
            const float2 tb = ((const float2*)(tkeys + (size_t)rb * ND))[lane];
            float a0 = qv.x - ta.x, a1 = qv.y - ta.y;
            float b0 = qv.x - tb.x, b1 = qv.y - tb.y;
            float sa = fmaf(a0, a0, a1 * a1);
            float sc = fmaf(b0, b0, b1 * b1);
#pragma unroll
            for (int o = 16; o > 0; o >>= 1) {
                sa += __shfl_xor_sync(0xffffffffu, sa, o);
                sc += __shfl_xor_sync(0xffffffffu, sc, o);
            }
            if (lane == 0) {
                sd[cb] = sa;
                if (has2) sd[cb2] = sc;
            }
        }
    }
    __syncthreads();

    // exact top-50 by iterative argmin over n candidates
    for (int k = 0; k < NK; k++) {
        float v = INF; int p = 0;
        for (int i = tid; i < n; i += 256)
            if (sd[i] < v) { v = sd[i]; p = i; }
#pragma unroll
        for (int o = 16; o > 0; o >>= 1) {
            float ov = __shfl_down_sync(0xffffffffu, v, o);
            int   op = __shfl_down_sync(0xffffffffu, p, o);
            if (ov < v) { v = ov; p = op; }
        }
        if (lane == 0) { frv[w] = v; frp[w] = p; }
        __syncthreads();
        if (tid == 0) {
            float bv = frv[0]; int bp = frp[0];
#pragma unroll
            for (int x = 1; x < 8; x++)
                if (frv[x] < bv) { bv = frv[x]; bp = frp[x]; }
            selv[k] = bv; sel2[k] = bp;
            sd[bp] = INF;
        }
        __syncthreads();
    }

    if (tid < NK) {
        float dv = selv[tid];
        float wgt = (dv < INF) ? 1.0f / (dv + 1e-3f) : 0.0f;
        ws[tid] = wgt;
        wv[tid] = wgt * tvals[cand[sel2[tid]]];
    }
    __syncthreads();
    if (tid == 0) {
        float sw = 0.f, sv = 0.f;
#pragma unroll
        for (int k = 0; k < NK; k++) { sw += ws[k]; sv += wv[k]; }
        out[q] = sv / sw;
    }
}

// ---------------------------------------------------------------------------
extern "C" void kernel_launch(void* const* d_in, const int* in_sizes, int n_in,
                              void* d_out, int out_size) {
    const float* keys  = (const float*)d_in[0];   // [1024, 64]
    const float* tkeys = (const float*)d_in[1];   // [500000, 64]
    const float* tvals = (const float*)d_in[2];   // [500000]
    float* out = (float*)d_out;                   // [1024]

    prep_t<<<NPAD / 256, 256>>>(tkeys);           // 1998 blocks, exact cover
    prep_q<<<4, 256>>>(keys);
    tau_kernel<<<NB, 256>>>();                    // thresholds + counter reset
    sweep_kernel<<<NR, 512>>>();
    merge_kernel<<<NB, 256>>>(keys, tkeys, tvals, out);
}

// round 15
// speedup vs baseline: 1.0079x; 1.0079x over previous
#include <cuda_runtime.h>
#include <cstdint>

#define NB 1024
#define NC 500000
#define ND 64
#define NK 50
#define NR 296                 // sweep CTAs = two per SM
#define RC 1728                // columns per range = 27 tiles x 64
#define TPT 27
#define TILE 64
#define NPAD (NR * RC)         // 511488 padded rows (same as before)
#define CAP 6144               // per-query candidate capacity
#define QS 25.0f
#define NSMP 4096              // tau sample size
#define SSTRIDE 122            // 4095*122 = 499590 < NC
#define NTAU 8                 // tau = 8th smallest sample score (~976 qualifiers)

typedef unsigned int u32;

// ------------------------- device-global scratch ---------------------------
__device__ __align__(16) unsigned char g_t8[(size_t)NPAD * 64];  // packed int8 table
__device__ int g_nint[NPAD];                                     // int norms (pad huge)
__device__ __align__(16) unsigned char g_q8[NB * 64];            // packed int8 queries
__device__ int g_tau[NB];                                        // per-query threshold
__device__ u32 g_cnt[NB];                                        // per-query counts
__device__ int g_cand[(size_t)NB * CAP];                         // candidate rows

// ------------------------------ helpers ------------------------------------
__device__ __forceinline__ u32 smem_u32(const void* p) {
    u32 a;
    asm("{ .reg .u64 t; cvta.to.shared.u64 t, %1; cvt.u32.u64 %0, t; }" : "=r"(a) : "l"(p));
    return a;
}
__device__ __forceinline__ void cpa16(u32 s, const void* g) {
    asm volatile("cp.async.cg.shared.global [%0], [%1], 16;" :: "r"(s), "l"(g));
}
__device__ __forceinline__ void cpa_commit() { asm volatile("cp.async.commit_group;" ::: "memory"); }
__device__ __forceinline__ void cpa_wait2()  { asm volatile("cp.async.wait_group 2;" ::: "memory"); }

__device__ __forceinline__ void quant_row(const float* v, u32* w, int& nint) {
    nint = 0;
#pragma unroll
    for (int j = 0; j < 16; j++) {
        u32 pk = 0;
#pragma unroll
        for (int e = 0; e < 4; e++) {
            int r = __float2int_rn(v[j * 4 + e] * QS);
            r = max(-127, min(127, r));
            nint += r * r;
            pk |= ((u32)(r & 255)) << (8 * e);
        }
        w[j] = pk;
    }
}
__device__ __forceinline__ void load16(const unsigned char* src, u32* w) {
    const uint4* p = (const uint4*)src;
#pragma unroll
    for (int i = 0; i < 4; i++) {
        uint4 x = p[i];
        w[4 * i] = x.x; w[4 * i + 1] = x.y; w[4 * i + 2] = x.z; w[4 * i + 3] = x.w;
    }
}

// ---------------------------------------------------------------------------
// prep_t: fp32 table -> packed int8 rows + int norms (padded rows never qualify)
// ---------------------------------------------------------------------------
__global__ void __launch_bounds__(256)
prep_t(const float* __restrict__ tkeys) {
    const int p = blockIdx.x * 256 + threadIdx.x;   // grid covers NPAD exactly
    u32 w[16];
    int nint;
    if (p < NC) {
        float v[ND];
        const float4* sp = (const float4*)(tkeys + (size_t)p * ND);
#pragma unroll
        for (int i = 0; i < 16; i++) {
            float4 x = __ldg(sp + i);
            v[4 * i] = x.x; v[4 * i + 1] = x.y; v[4 * i + 2] = x.z; v[4 * i + 3] = x.w;
        }
        quant_row(v, w, nint);
    } else {
#pragma unroll
        for (int i = 0; i < 16; i++) w[i] = 0;
        nint = 1 << 29;                              // never below any tau
    }
    uint4* dst = (uint4*)(g_t8 + (size_t)p * 64);
    dst[0] = make_uint4(w[0], w[1], w[2], w[3]);
    dst[1] = make_uint4(w[4], w[5], w[6], w[7]);
    dst[2] = make_uint4(w[8], w[9], w[10], w[11]);
    dst[3] = make_uint4(w[12], w[13], w[14], w[15]);
    g_nint[p] = nint;
}

// prep_q: quantize queries
__global__ void __launch_bounds__(256)
prep_q(const float* __restrict__ keys) {
    const int p = blockIdx.x * 256 + threadIdx.x;
    if (p >= NB) return;
    float v[ND];
    const float4* sp = (const float4*)(keys + (size_t)p * ND);
#pragma unroll
    for (int i = 0; i < 16; i++) {
        float4 x = __ldg(sp + i);
        v[4 * i] = x.x; v[4 * i + 1] = x.y; v[4 * i + 2] = x.z; v[4 * i + 3] = x.w;
    }
    u32 w[16]; int nint;
    quant_row(v, w, nint);
    uint4* dst = (uint4*)(g_q8 + (size_t)p * 64);
    dst[0] = make_uint4(w[0], w[1], w[2], w[3]);
    dst[1] = make_uint4(w[4], w[5], w[6], w[7]);
    dst[2] = make_uint4(w[8], w[9], w[10], w[11]);
    dst[3] = make_uint4(w[12], w[13], w[14], w[15]);
}

// ---------------------------------------------------------------------------
// tau_kernel: per-query threshold from 4096-row sample; also resets counter
// ---------------------------------------------------------------------------
__global__ void __launch_bounds__(256)
tau_kernel() {
    __shared__ int s_s[NSMP];                 // 16KB sample scores
    __shared__ int rv[8], rp[8];
    __shared__ int s_tau;

    const int q = blockIdx.x, tid = threadIdx.x;
    const int w = tid >> 5, lane = tid & 31;

    u32 qw[16];
    load16(g_q8 + (size_t)q * 64, qw);

#pragma unroll
    for (int i = 0; i < NSMP / 256; i++) {
        const int j = tid + i * 256;
        const int r = j * SSTRIDE;
        u32 tw[16];
        load16(g_t8 + (size_t)r * 64, tw);
        int d = 0;
#pragma unroll
        for (int k = 0; k < 16; k++) d = __dp4a((int)tw[k], (int)qw[k], d);
        s_s[j] = g_nint[r] - 2 * d;
    }
    __syncthreads();

    for (int k = 0; k < NTAU; k++) {
        int v = 0x7FFFFFFF, p = 0;
        for (int i = tid; i < NSMP; i += 256)
            if (s_s[i] < v) { v = s_s[i]; p = i; }
#pragma unroll
        for (int o = 16; o > 0; o >>= 1) {
            int ov = __shfl_down_sync(0xffffffffu, v, o);
            int op = __shfl_down_sync(0xffffffffu, p, o);
            if (ov < v) { v = ov; p = op; }
        }
        if (lane == 0) { rv[w] = v; rp[w] = p; }
        __syncthreads();
        if (tid == 0) {
            int bv = rv[0], bp = rp[0];
#pragma unroll
            for (int x = 1; x < 8; x++)
                if (rv[x] < bv) { bv = rv[x]; bp = rp[x]; }
            s_s[bp] = 0x7FFFFFFF;
            if (k == NTAU - 1) s_tau = bv;
        }
        __syncthreads();
    }
    if (tid == 0) { g_tau[q] = s_tau; g_cnt[q] = 0u; }
}

// ---------------------------------------------------------------------------
// sweep: dp4a sweep at 2 CTAs/SM (8 warps/SMSP). 296 CTAs x 512 threads,
// 2 queries/thread, single register column buffer, 64-col smem tiles.
// Co-resident CTAs have independent barriers -> decorrelated stalls.
// ---------------------------------------------------------------------------
__global__ void __launch_bounds__(512, 2)
sweep_kernel() {
    __shared__ __align__(16) u32 s_t[3][TILE * 16];   // 3 x 4KB tile
    __shared__ __align__(16) int s_n[3][TILE];        // 3 x 256B norms

    const int tid = threadIdx.x;
    const int range = blockIdx.x;
    const int q0 = tid * 2, q1 = q0 + 1;
    const u32 sbt = smem_u32(&s_t[0][0]);
    const u32 sbn = smem_u32(&s_n[0][0]);

    u32 q0w[16], q1w[16];
    load16(g_q8 + (size_t)q0 * 64, q0w);
    load16(g_q8 + (size_t)q1 * 64, q1w);
    const int t0 = g_tau[q0] + 1;     // strict < t  <=>  s <= tau
    const int t1 = g_tau[q1] + 1;

    const size_t rbase = (size_t)range * RC;
    auto prefetch = [&](int t, int st) {
        const unsigned char* src = g_t8 + (rbase + (size_t)t * TILE) * 64;
        if (tid < 256) cpa16(sbt + st * 4096 + tid * 16, src + tid * 16);
        if (tid < 16)
            cpa16(sbn + st * 256 + tid * 16,
                  (const unsigned char*)(g_nint + rbase + (size_t)t * TILE) + tid * 16);
        cpa_commit();
    };

    prefetch(0, 0); prefetch(1, 1); prefetch(2, 2);

    for (int t = 0; t < TPT; t++) {
        const int st = t % 3;
        cpa_wait2();
        __syncthreads();

        const u32* tp = s_t[st];
        const int* np = s_n[st];
        const int pbase = range * RC + t * TILE;

#pragma unroll 4
        for (int c = 0; c < TILE; c++) {
            u32 X[16];
            load16((const unsigned char*)(tp + c * 16), X);
            const int n = np[c];

            int a0a = 0, a0b = 0, a1a = 0, a1b = 0;   // 4 independent chains
#pragma unroll
            for (int j = 0; j < 8; j++) {
                a0a = __dp4a((int)X[j],     (int)q0w[j],     a0a);
                a1a = __dp4a((int)X[j],     (int)q1w[j],     a1a);
                a0b = __dp4a((int)X[j + 8], (int)q0w[j + 8], a0b);
                a1b = __dp4a((int)X[j + 8], (int)q1w[j + 8], a1b);
            }
            const int s0 = n - 2 * (a0a + a0b);
            const int s1 = n - 2 * (a1a + a1b);

            if (min(s0 - t0, s1 - t1) < 0) {
                const int p0 = pbase + c;
                if (s0 < t0) {
                    u32 i = atomicAdd(&g_cnt[q0], 1u);
                    if (i < CAP) g_cand[(size_t)q0 * CAP + i] = p0;
                }
                if (s1 < t1) {
                    u32 i = atomicAdd(&g_cnt[q1], 1u);
                    if (i < CAP) g_cand[(size_t)q1 * CAP + i] = p0;
                }
            }
        }

        __syncthreads();
        if (t + 3 < TPT) prefetch(t + 3, st);
        else cpa_commit();
    }
}

// ---------------------------------------------------------------------------
// merge: exact fp32 rerank (ILP-2) -> exact top-50 -> weighted average
// ---------------------------------------------------------------------------
__global__ void __launch_bounds__(256)
merge_kernel(const float* __restrict__ keys, const float* __restrict__ tkeys,
             const float* __restrict__ tvals, float* __restrict__ out) {
    __shared__ float sd[CAP];                 // 24KB exact distances
    __shared__ __align__(16) float qs[ND];
    __shared__ float frv[8]; __shared__ int frp[8];
    __shared__ float selv[NK]; __shared__ int sel2[NK];
    __shared__ float ws[NK], wv[NK];

    const int q = blockIdx.x, tid = threadIdx.x;
    const int w = tid >> 5, lane = tid & 31;
    const float INF = __int_as_float(0x7f800000);
    const int n = min((int)g_cnt[q], CAP);
    const int* cand = g_cand + (size_t)q * CAP;

    if (tid < ND) qs[tid] = keys[(size_t)q * ND + tid];
    __syncthreads();

    // exact squared distances: warp per candidate, 2 rows in flight
    {
        const float2 qv = ((const float2*)qs)[lane];
        for (int cb = w; cb < n; cb += 16) {
            const int cb2 = cb + 8;
            const bool has2 = cb2 < n;
            const int ra = cand[cb];
            const int rb = cand[has2 ? cb2 : cb];
            const float2 ta = ((const float2*)(tkeys + (size_t)ra * ND))[lane];
            const float2 tb = ((const float2*)(tkeys + (size_t)rb * ND))[lane];
            float a0 = qv.x - ta.x, a1 = qv.y - ta.y;
            float b0 = qv.x - tb.x, b1 = qv.y - tb.y;
            float sa = fmaf(a0, a0, a1 * a1);
            float sc = fmaf(b0, b0, b1 * b1);
#pragma unroll
            for (int o = 16; o > 0; o >>= 1) {
                sa += __shfl_xor_sync(0xffffffffu, sa, o);
                sc += __shfl_xor_sync(0xffffffffu, sc, o);
            }
            if (lane == 0) {
                sd[cb] = sa;
                if (has2) sd[cb2] = sc;
            }
        }
    }
    __syncthreads();

    // exact top-50 by iterative argmin over n candidates
    for (int k = 0; k < NK; k++) {
        float v = INF; int p = 0;
        for (int i = tid; i < n; i += 256)
            if (sd[i] < v) { v = sd[i]; p = i; }
#pragma unroll
        for (int o = 16; o > 0; o >>= 1) {
            float ov = __shfl_down_sync(0xffffffffu, v, o);
            int   op = __shfl_down_sync(0xffffffffu, p, o);
            if (ov < v) { v = ov; p = op; }
        }
        if (lane == 0) { frv[w] = v; frp[w] = p; }
        __syncthreads();
        if (tid == 0) {
            float bv = frv[0]; int bp = frp[0];
#pragma unroll
            for (int x = 1; x < 8; x++)
                if (frv[x] < bv) { bv = frv[x]; bp = frp[x]; }
            selv[k] = bv; sel2[k] = bp;
            sd[bp] = INF;
        }
        __syncthreads();
    }

    if (tid < NK) {
        float dv = selv[tid];
        float wgt = (dv < INF) ? 1.0f / (dv + 1e-3f) : 0.0f;
        ws[tid] = wgt;
        wv[tid] = wgt * tvals[cand[sel2[tid]]];
    }
    __syncthreads();
    if (tid == 0) {
        float sw = 0.f, sv = 0.f;
#pragma unroll
        for (int k = 0; k < NK; k++) { sw += ws[k]; sv += wv[k]; }
        out[q] = sv / sw;
    }
}

// ---------------------------------------------------------------------------
extern "C" void kernel_launch(void* const* d_in, const int* in_sizes, int n_in,
                              void* d_out, int out_size) {
    const float* keys  = (const float*)d_in[0];   // [1024, 64]
    const float* tkeys = (const float*)d_in[1];   // [500000, 64]
    const float* tvals = (const float*)d_in[2];   // [500000]
    float* out = (float*)d_out;                   // [1024]

    prep_t<<<NPAD / 256, 256>>>(tkeys);           // 1998 blocks, exact cover
    prep_q<<<4, 256>>>(keys);
    tau_kernel<<<NB, 256>>>();                    // thresholds + counter reset
    sweep_kernel<<<NR, 512>>>();
    merge_kernel<<<NB, 256>>>(keys, tkeys, tvals, out);
}